// round 1
// baseline (speedup 1.0000x reference)
#include <cuda_runtime.h>
#include <cuda_bf16.h>

// SimpleCodebook: VQ nearest-neighbor lookup.
//   X: [8,1024,512] fp32 -> flatten [8192, 512]
//   E: [8192, 512] fp32 codebook
//   out: quantize [8192,512] fp32 (+ indices [8192] appended as float if room)
//
// score[n,k] = 2 * dot(x_n, e_k) - ||e_k||^2   (x^2 term drops out of argmax)
// argmax ties broken toward LOWER index (matches jnp.argmax first-occurrence).

#define NQ   8192      // queries
#define NC   8192      // codes
#define DD   512       // dim
#define BM   128
#define BN   128
#define BK   16
#define NSPLIT 8
#define CPB  (NC / NSPLIT)   // codes per block (N-split chunk) = 1024

// Scratch (no allocations allowed -> device globals)
__device__ float g_esq [NC];
__device__ float g_pval[NSPLIT * NQ];
__device__ int   g_pidx[NSPLIT * NQ];

// ---------------------------------------------------------------------------
// Packed fp32x2 helpers (Blackwell: FFMA2 only reachable via PTX fma.rn.f32x2)
// ---------------------------------------------------------------------------
__device__ __forceinline__ void ffma2(unsigned long long& c,
                                      unsigned long long a,
                                      unsigned long long b) {
    asm("fma.rn.f32x2 %0, %1, %2, %3;" : "=l"(c) : "l"(a), "l"(b), "l"(c));
}

__device__ __forceinline__ unsigned long long dup2(float x) {
    unsigned long long r;
    asm("mov.b64 %0, {%1, %1};" : "=l"(r) : "f"(x));
    return r;
}

__device__ __forceinline__ float2 unpack2(unsigned long long v) {
    float2 r;
    asm("mov.b64 {%0, %1}, %2;" : "=f"(r.x), "=f"(r.y) : "l"(v));
    return r;
}

// ---------------------------------------------------------------------------
// Kernel 1: ||e_k||^2 per code row
// ---------------------------------------------------------------------------
__global__ void esq_kernel(const float* __restrict__ E) {
    int code = blockIdx.x;
    const float4* row = reinterpret_cast<const float4*>(E + (long long)code * DD);
    float4 v = row[threadIdx.x];              // 128 threads x float4 = 512 floats
    float s = v.x * v.x + v.y * v.y + v.z * v.z + v.w * v.w;
    #pragma unroll
    for (int o = 16; o; o >>= 1) s += __shfl_down_sync(0xFFFFFFFFu, s, o);
    __shared__ float ws[4];
    if ((threadIdx.x & 31) == 0) ws[threadIdx.x >> 5] = s;
    __syncthreads();
    if (threadIdx.x == 0) g_esq[code] = ws[0] + ws[1] + ws[2] + ws[3];
}

// ---------------------------------------------------------------------------
// Kernel 2: fused GEMM (2*X@E^T - e_sq) + per-row partial argmax
//   grid = (NQ/BM, NSPLIT), block = 256 threads
//   thread (tx,ty), tx=tid&15, ty=tid>>4: rows ty*8..ty*8+7, cols tx*8..tx*8+7
// ---------------------------------------------------------------------------
__global__ __launch_bounds__(256, 1)
void vq_partial_kernel(const float* __restrict__ X, const float* __restrict__ E) {
    __shared__ float As[BK][BM];    // X tile, transposed: As[d][m]
    __shared__ float Bs[BK][BN];    // E tile, transposed: Bs[d][n]
    __shared__ float esq_s[CPB];

    const int tid = threadIdx.x;
    const int tx = tid & 15;
    const int ty = tid >> 4;
    const int m0 = blockIdx.x * BM;
    const int split = blockIdx.y;
    const int c_base = split * CPB;

    for (int i = tid; i < CPB; i += 256) esq_s[i] = g_esq[c_base + i];

    float best[8];
    int   bidx[8];
    #pragma unroll
    for (int i = 0; i < 8; i++) { best[i] = -3.4e38f; bidx[i] = 0; }

    for (int nt = 0; nt < CPB; nt += BN) {
        const int n0 = c_base + nt;

        unsigned long long acc[8][4];
        #pragma unroll
        for (int i = 0; i < 8; i++)
            #pragma unroll
            for (int p = 0; p < 4; p++) acc[i][p] = 0ULL;

        for (int k0 = 0; k0 < DD; k0 += BK) {
            // ---- load tiles (each thread: 2 float4 of X, 2 float4 of E) ----
            #pragma unroll
            for (int i = 0; i < 2; i++) {
                int lin = tid + i * 256;           // 0..511
                int row = lin >> 2;                // 0..127
                int c4  = lin & 3;                 // 0..3  -> 4 floats each
                float4 v = *reinterpret_cast<const float4*>(
                    X + (long long)(m0 + row) * DD + k0 + c4 * 4);
                As[c4 * 4 + 0][row] = v.x;
                As[c4 * 4 + 1][row] = v.y;
                As[c4 * 4 + 2][row] = v.z;
                As[c4 * 4 + 3][row] = v.w;
                float4 w = *reinterpret_cast<const float4*>(
                    E + (long long)(n0 + row) * DD + k0 + c4 * 4);
                Bs[c4 * 4 + 0][row] = w.x;
                Bs[c4 * 4 + 1][row] = w.y;
                Bs[c4 * 4 + 2][row] = w.z;
                Bs[c4 * 4 + 3][row] = w.w;
            }
            __syncthreads();

            // ---- 128x128x16 register-tile compute, packed f32x2 FMAs ----
            #pragma unroll
            for (int d = 0; d < BK; d++) {
                float4 a0 = *reinterpret_cast<const float4*>(&As[d][ty * 8]);
                float4 a1 = *reinterpret_cast<const float4*>(&As[d][ty * 8 + 4]);
                ulonglong2 b0 = *reinterpret_cast<const ulonglong2*>(&Bs[d][tx * 8]);
                ulonglong2 b1 = *reinterpret_cast<const ulonglong2*>(&Bs[d][tx * 8 + 4]);
                unsigned long long ad[8];
                ad[0] = dup2(a0.x); ad[1] = dup2(a0.y);
                ad[2] = dup2(a0.z); ad[3] = dup2(a0.w);
                ad[4] = dup2(a1.x); ad[5] = dup2(a1.y);
                ad[6] = dup2(a1.z); ad[7] = dup2(a1.w);
                unsigned long long bp[4] = { b0.x, b0.y, b1.x, b1.y };
                #pragma unroll
                for (int i = 0; i < 8; i++) {
                    #pragma unroll
                    for (int p = 0; p < 4; p++) ffma2(acc[i][p], ad[i], bp[p]);
                }
            }
            __syncthreads();
        }

        // ---- fold this 128x128 score tile into running per-row best ----
        #pragma unroll
        for (int i = 0; i < 8; i++) {
            #pragma unroll
            for (int p = 0; p < 4; p++) {
                float2 dv = unpack2(acc[i][p]);
                int col = nt + tx * 8 + 2 * p;               // within chunk
                float s0 = 2.0f * dv.x - esq_s[col];
                float s1 = 2.0f * dv.y - esq_s[col + 1];
                if (s0 > best[i]) { best[i] = s0; bidx[i] = c_base + col; }
                if (s1 > best[i]) { best[i] = s1; bidx[i] = c_base + col + 1; }
            }
        }
    }

    // ---- reduce across the 16 tx-threads sharing each row ----
    __syncthreads();                      // done reading As/Bs; reuse as scratch
    float* shv = &As[0][0];               // 2048 floats  (128 rows x 16)
    int*   shi = reinterpret_cast<int*>(&Bs[0][0]);
    #pragma unroll
    for (int i = 0; i < 8; i++) {
        int row = ty * 8 + i;
        shv[row * 16 + tx] = best[i];
        shi[row * 16 + tx] = bidx[i];
    }
    __syncthreads();
    if (tid < 128) {
        int row = tid;
        float bv = shv[row * 16];
        int   bi = shi[row * 16];
        #pragma unroll
        for (int t = 1; t < 16; t++) {
            float v  = shv[row * 16 + t];
            int   ii = shi[row * 16 + t];
            if (v > bv || (v == bv && ii < bi)) { bv = v; bi = ii; }
        }
        g_pval[split * NQ + m0 + row] = bv;
        g_pidx[split * NQ + m0 + row] = bi;
    }
}

// ---------------------------------------------------------------------------
// Kernel 3: reduce NSPLIT partials per row, gather codebook row, write index
// ---------------------------------------------------------------------------
__global__ void finalize_kernel(const float* __restrict__ E,
                                float* __restrict__ out,
                                int write_idx) {
    int row = blockIdx.x;
    __shared__ int s_idx;
    if (threadIdx.x == 0) {
        float bv = g_pval[row];
        int   bi = g_pidx[row];
        #pragma unroll
        for (int s = 1; s < NSPLIT; s++) {
            float v  = g_pval[s * NQ + row];
            int   ii = g_pidx[s * NQ + row];
            if (v > bv || (v == bv && ii < bi)) { bv = v; bi = ii; }
        }
        s_idx = bi;
        if (write_idx) out[(long long)NQ * DD + row] = (float)bi;
    }
    __syncthreads();
    int idx = s_idx;
    float4 v = *reinterpret_cast<const float4*>(
        E + (long long)idx * DD + threadIdx.x * 4);
    *reinterpret_cast<float4*>(out + (long long)row * DD + threadIdx.x * 4) = v;
}

// ---------------------------------------------------------------------------
extern "C" void kernel_launch(void* const* d_in, const int* in_sizes, int n_in,
                              void* d_out, int out_size) {
    const float* X = (const float*)d_in[0];   // [8192, 512]
    const float* E = (const float*)d_in[1];   // [8192, 512]
    float* out = (float*)d_out;

    esq_kernel<<<NC, 128>>>(E);
    vq_partial_kernel<<<dim3(NQ / BM, NSPLIT), 256>>>(X, E);
    int write_idx = (out_size >= NQ * DD + NQ) ? 1 : 0;
    finalize_kernel<<<NQ, 128>>>(E, out, write_idx);
}

// round 3
// speedup vs baseline: 3.5694x; 3.5694x over previous
#include <cuda_runtime.h>
#include <cuda_fp16.h>
#include <cstdint>

// SimpleCodebook VQ via mma.sync fp16 2-split GEMM (3 products: x0e0+x0e1+x1e0)
//   score[n,k] = 2*x_n . e_k - ||e_k||^2    (x^2 drops out of argmax)
//   X scaled by 2 at split time. fp32 accumulation in HMMA.

#define NQ 8192
#define NC 8192
#define DD 512
#define BMT 128             // CTA tile M
#define BNT 128             // CTA tile N
#define BK  64              // K chunk (fp16) -> 128B rows
#define NKC (DD / BK)       // 8
#define NSPLITC (NC / BNT)  // 64

#define NSTG 3
#define STG_BYTES 65536     // 4 tiles (A0,A1,B0,B1) x 16KB
#define OFF_ESQ 0           // 128 floats = 512B
#define OFF_RDV 512         // 128x4 floats = 2KB
#define OFF_RDI 2560        // 128x4 ints   = 2KB
#define OFF_STG 5120
#define SMEM_TOTAL (OFF_STG + NSTG * STG_BYTES)   // 201728

// ---- device global scratch ----
__device__ __half g_X0[NQ * DD], g_X1[NQ * DD];
__device__ __half g_E0[NC * DD], g_E1[NC * DD];
__device__ float g_esq[NC];
__device__ float g_pval[NSPLITC * NQ];
__device__ int   g_pidx[NSPLITC * NQ];

static __device__ __forceinline__ uint32_t smem_u32(const void* p) {
    uint32_t a;
    asm("{ .reg .u64 t; cvta.to.shared.u64 t, %1; cvt.u32.u64 %0, t; }" : "=r"(a) : "l"(p));
    return a;
}
static __device__ __forceinline__ uint32_t swz(uint32_t o) { return o ^ ((o >> 3) & 0x70); }

static __device__ __forceinline__ void cp16(uint32_t dst, const void* src) {
    asm volatile("cp.async.cg.shared.global [%0], [%1], 16;" :: "r"(dst), "l"(src) : "memory");
}
#define CP_COMMIT() asm volatile("cp.async.commit_group;" ::: "memory")
#define CP_WAIT0()  asm volatile("cp.async.wait_group 0;" ::: "memory")
#define CP_WAIT1()  asm volatile("cp.async.wait_group 1;" ::: "memory")

static __device__ __forceinline__ void ldsm_x4(uint32_t* r, uint32_t addr) {
    asm volatile("ldmatrix.sync.aligned.m8n8.x4.shared.b16 {%0,%1,%2,%3}, [%4];"
                 : "=r"(r[0]), "=r"(r[1]), "=r"(r[2]), "=r"(r[3]) : "r"(addr));
}
static __device__ __forceinline__ void ldsm_x2(uint32_t* r, uint32_t addr) {
    asm volatile("ldmatrix.sync.aligned.m8n8.x2.shared.b16 {%0,%1}, [%2];"
                 : "=r"(r[0]), "=r"(r[1]) : "r"(addr));
}
static __device__ __forceinline__ void hmma(float* c, const uint32_t* a, const uint32_t* b) {
    asm volatile(
        "mma.sync.aligned.m16n8k16.row.col.f32.f16.f16.f32 "
        "{%0,%1,%2,%3}, {%4,%5,%6,%7}, {%8,%9}, {%0,%1,%2,%3};"
        : "+f"(c[0]), "+f"(c[1]), "+f"(c[2]), "+f"(c[3])
        : "r"(a[0]), "r"(a[1]), "r"(a[2]), "r"(a[3]), "r"(b[0]), "r"(b[1]));
}

// ---------------------------------------------------------------------------
// Kernel 1: split 2*X and E into 2 fp16 terms each; compute ||e||^2
// ---------------------------------------------------------------------------
static __device__ __forceinline__ void split2(float v, __half& h0, __half& h1) {
    h0 = __float2half_rn(v);
    h1 = __float2half_rn(v - __half2float(h0));
}

__global__ void convert_kernel(const float* __restrict__ X, const float* __restrict__ E) {
    int row = blockIdx.x;
    int t = threadIdx.x;                     // 128
    size_t base = (size_t)row * DD + t * 4;
    {
        float4 v = *reinterpret_cast<const float4*>(X + base);
        float s[4] = {2.f * v.x, 2.f * v.y, 2.f * v.z, 2.f * v.w};
        __half h0[4], h1[4];
        #pragma unroll
        for (int i = 0; i < 4; i++) split2(s[i], h0[i], h1[i]);
        *reinterpret_cast<__half2*>(&g_X0[base])     = __half2{h0[0], h0[1]};
        *reinterpret_cast<__half2*>(&g_X0[base + 2]) = __half2{h0[2], h0[3]};
        *reinterpret_cast<__half2*>(&g_X1[base])     = __half2{h1[0], h1[1]};
        *reinterpret_cast<__half2*>(&g_X1[base + 2]) = __half2{h1[2], h1[3]};
    }
    {
        float4 v = *reinterpret_cast<const float4*>(E + base);
        float s[4] = {v.x, v.y, v.z, v.w};
        __half h0[4], h1[4];
        #pragma unroll
        for (int i = 0; i < 4; i++) split2(s[i], h0[i], h1[i]);
        *reinterpret_cast<__half2*>(&g_E0[base])     = __half2{h0[0], h0[1]};
        *reinterpret_cast<__half2*>(&g_E0[base + 2]) = __half2{h0[2], h0[3]};
        *reinterpret_cast<__half2*>(&g_E1[base])     = __half2{h1[0], h1[1]};
        *reinterpret_cast<__half2*>(&g_E1[base + 2]) = __half2{h1[2], h1[3]};

        float sq = v.x * v.x + v.y * v.y + v.z * v.z + v.w * v.w;
        #pragma unroll
        for (int o = 16; o; o >>= 1) sq += __shfl_down_sync(0xFFFFFFFFu, sq, o);
        __shared__ float ws[4];
        if ((t & 31) == 0) ws[t >> 5] = sq;
        __syncthreads();
        if (t == 0) g_esq[row] = ws[0] + ws[1] + ws[2] + ws[3];
    }
}

// ---------------------------------------------------------------------------
// Kernel 2: HMMA GEMM + per-row partial argmax.  grid (64, 64), 256 threads.
// ---------------------------------------------------------------------------
static __device__ __forceinline__ void load_stage(uint32_t sb, int s, int kc,
                                                  int m0, int cb0, int tid) {
    uint32_t stg = sb + OFF_STG + s * STG_BYTES;
    #pragma unroll
    for (int tile = 0; tile < 4; tile++) {
        const __half* src_base = (tile == 0) ? g_X0 : (tile == 1) ? g_X1
                               : (tile == 2) ? g_E0 : g_E1;
        int rb = (tile < 2) ? m0 : cb0;
        #pragma unroll
        for (int i = 0; i < 4; i++) {
            int cid = tid + i * 256;              // 0..1023
            int row = cid >> 3;
            int c16 = cid & 7;
            const __half* src = src_base + (size_t)(rb + row) * DD + kc * BK + c16 * 8;
            uint32_t dst = stg + tile * 16384 + swz((uint32_t)(row * 128 + c16 * 16));
            cp16(dst, src);
        }
    }
    CP_COMMIT();
}

__global__ __launch_bounds__(256, 1)
void vq_mma_kernel() {
    extern __shared__ char smem[];
    const uint32_t sb = smem_u32(smem);
    const int tid = threadIdx.x;
    const int lane = tid & 31;
    const int wid = tid >> 5;
    const int warp_m = wid >> 2;         // 0..1  (64 rows)
    const int warp_n = wid & 3;          // 0..3  (32 cols)
    const int m0 = blockIdx.x * BMT;
    const int cb0 = blockIdx.y * BNT;

    float* es = reinterpret_cast<float*>(smem + OFF_ESQ);
    for (int i = tid; i < BNT; i += 256) es[i] = g_esq[cb0 + i];

    float acc[4][4][4];
    #pragma unroll
    for (int mf = 0; mf < 4; mf++)
        #pragma unroll
        for (int nf = 0; nf < 4; nf++)
            #pragma unroll
            for (int c = 0; c < 4; c++) acc[mf][nf][c] = 0.f;

    // prologue: stages 0,1
    load_stage(sb, 0, 0, m0, cb0, tid);
    load_stage(sb, 1, 1, m0, cb0, tid);

    const int pa[3] = {0, 0, 1};
    const int pb[3] = {0, 1, 0};

    for (int kc = 0; kc < NKC; kc++) {
        if (kc == NKC - 1) CP_WAIT0(); else CP_WAIT1();
        __syncthreads();
        if (kc + 2 < NKC) load_stage(sb, (kc + 2) % NSTG, kc + 2, m0, cb0, tid);

        uint32_t stg = sb + OFF_STG + (kc % NSTG) * STG_BYTES;
        #pragma unroll
        for (int p = 0; p < 3; p++) {
            uint32_t Ab = stg + pa[p] * 16384;
            uint32_t Bb = stg + 32768 + pb[p] * 16384;
            #pragma unroll
            for (int ks = 0; ks < 4; ks++) {
                uint32_t a[4][4], b[4][2];
                #pragma unroll
                for (int mf = 0; mf < 4; mf++) {
                    int row = warp_m * 64 + mf * 16 + (lane & 15);
                    int kb = ks * 32 + (lane >> 4) * 16;
                    ldsm_x4(a[mf], Ab + swz((uint32_t)(row * 128 + kb)));
                }
                #pragma unroll
                for (int nf = 0; nf < 4; nf++) {
                    int rn = warp_n * 32 + nf * 8 + (lane & 7);
                    int kb = ks * 32 + ((lane >> 3) & 1) * 16;
                    ldsm_x2(b[nf], Bb + swz((uint32_t)(rn * 128 + kb)));
                }
                #pragma unroll
                for (int mf = 0; mf < 4; mf++)
                    #pragma unroll
                    for (int nf = 0; nf < 4; nf++)
                        hmma(acc[mf][nf], a[mf], b[nf]);
            }
        }
        __syncthreads();
    }

    // ---- epilogue: argmax over this CTA's 128 cols ----
    // slot = mf*2 + h ; row = warp_m*64 + mf*16 + (lane>>2) + h*8
    float best[8];
    int   bidx[8];
    #pragma unroll
    for (int i = 0; i < 8; i++) { best[i] = -3.4e38f; bidx[i] = 0; }

    #pragma unroll
    for (int mf = 0; mf < 4; mf++) {
        #pragma unroll
        for (int nf = 0; nf < 4; nf++) {
            int colb = warp_n * 32 + nf * 8 + (lane & 3) * 2;
            float s0 = acc[mf][nf][0] - es[colb];
            float s1 = acc[mf][nf][1] - es[colb + 1];
            float s2 = acc[mf][nf][2] - es[colb];
            float s3 = acc[mf][nf][3] - es[colb + 1];
            int sl0 = mf * 2, sl1 = mf * 2 + 1;
            if (s0 > best[sl0]) { best[sl0] = s0; bidx[sl0] = colb; }
            if (s1 > best[sl0]) { best[sl0] = s1; bidx[sl0] = colb + 1; }
            if (s2 > best[sl1]) { best[sl1] = s2; bidx[sl1] = colb; }
            if (s3 > best[sl1]) { best[sl1] = s3; bidx[sl1] = colb + 1; }
        }
    }
    // reduce across the 4 lanes (same rows, different cols)
    #pragma unroll
    for (int off = 1; off <= 2; off <<= 1) {
        #pragma unroll
        for (int i = 0; i < 8; i++) {
            float vv = __shfl_xor_sync(0xFFFFFFFFu, best[i], off);
            int   ii = __shfl_xor_sync(0xFFFFFFFFu, bidx[i], off);
            if (vv > best[i] || (vv == best[i] && ii < bidx[i])) {
                best[i] = vv; bidx[i] = ii;
            }
        }
    }
    float* rdv = reinterpret_cast<float*>(smem + OFF_RDV);
    int*   rdi = reinterpret_cast<int*>(smem + OFF_RDI);
    if ((lane & 3) == 0) {
        #pragma unroll
        for (int i = 0; i < 8; i++) {
            int row = warp_m * 64 + (i >> 1) * 16 + (lane >> 2) + (i & 1) * 8;
            rdv[row * 4 + warp_n] = best[i];
            rdi[row * 4 + warp_n] = bidx[i];
        }
    }
    __syncthreads();
    if (tid < BMT) {
        float bv = rdv[tid * 4];
        int   bi = rdi[tid * 4];
        #pragma unroll
        for (int w = 1; w < 4; w++) {
            float v  = rdv[tid * 4 + w];
            int   ii = rdi[tid * 4 + w];
            if (v > bv || (v == bv && ii < bi)) { bv = v; bi = ii; }
        }
        g_pval[blockIdx.y * NQ + m0 + tid] = bv;
        g_pidx[blockIdx.y * NQ + m0 + tid] = cb0 + bi;
    }
}

// ---------------------------------------------------------------------------
// Kernel 3: reduce 64 partials per row, gather codebook row, write index
// ---------------------------------------------------------------------------
__global__ void finalize_kernel(const float* __restrict__ E,
                                float* __restrict__ out, int write_idx) {
    int row = blockIdx.x;
    __shared__ float sv[64];
    __shared__ int   si[64];
    __shared__ int   s_idx;
    int t = threadIdx.x;
    if (t < 64) {
        sv[t] = g_pval[t * NQ + row];
        si[t] = g_pidx[t * NQ + row];
    }
    __syncthreads();
    if (t == 0) {
        float bv = sv[0]; int bi = si[0];
        #pragma unroll
        for (int s = 1; s < 64; s++) {
            float v = sv[s]; int ii = si[s];
            if (v > bv || (v == bv && ii < bi)) { bv = v; bi = ii; }
        }
        s_idx = bi;
        if (write_idx) out[(size_t)NQ * DD + row] = (float)bi;
    }
    __syncthreads();
    int idx = s_idx;
    float4 v = *reinterpret_cast<const float4*>(E + (size_t)idx * DD + t * 4);
    *reinterpret_cast<float4*>(out + (size_t)row * DD + t * 4) = v;
}

// ---------------------------------------------------------------------------
extern "C" void kernel_launch(void* const* d_in, const int* in_sizes, int n_in,
                              void* d_out, int out_size) {
    const float* X = (const float*)d_in[0];
    const float* E = (const float*)d_in[1];
    float* out = (float*)d_out;

    static int attr_done = 0;
    if (!attr_done) {
        cudaFuncSetAttribute(vq_mma_kernel,
                             cudaFuncAttributeMaxDynamicSharedMemorySize, SMEM_TOTAL);
        attr_done = 1;
    }

    convert_kernel<<<NQ, 128>>>(X, E);
    vq_mma_kernel<<<dim3(NQ / BMT, NC / BNT), 256, SMEM_TOTAL>>>();
    int write_idx = (out_size >= NQ * DD + NQ) ? 1 : 0;
    finalize_kernel<<<NQ, 128>>>(E, out, write_idx);
}

// round 4
// speedup vs baseline: 4.2069x; 1.1786x over previous
#include <cuda_runtime.h>
#include <cuda_fp16.h>
#include <cstdint>

// SimpleCodebook VQ via mma.sync fp16 2-split GEMM (3 products: x0e0+x0e1+x1e0)
//   score[n,k] = 2*x_n . e_k - ||e_k||^2    (x^2 drops out of argmax)
//   X scaled by 2 at split time. fp32 accumulation in HMMA.
//   R4: 128x256 CTA tile, warp tile 64x64, fragment reuse across products.

#define NQ 8192
#define NC 8192
#define DD 512
#define BMT 128             // CTA tile M
#define BNT 256             // CTA tile N
#define BK  64              // K chunk (fp16) -> 128B rows
#define NKC (DD / BK)       // 8
#define NSPLITC (NC / BNT)  // 32

#define NSTG 2
#define STG_BYTES 98304     // A0(16K) A1(16K) B0(32K) B1(32K)
#define OFF_ESQ 0           // 256 floats = 1KB
#define OFF_RDV 1024        // 128x4 floats = 2KB
#define OFF_RDI 3072        // 128x4 ints   = 2KB
#define OFF_STG 5120
#define SMEM_TOTAL (OFF_STG + NSTG * STG_BYTES)   // 201728

// ---- device global scratch ----
__device__ __half g_X0[NQ * DD], g_X1[NQ * DD];
__device__ __half g_E0[NC * DD], g_E1[NC * DD];
__device__ float g_esq[NC];
__device__ float g_pval[NSPLITC * NQ];
__device__ int   g_pidx[NSPLITC * NQ];

static __device__ __forceinline__ uint32_t smem_u32(const void* p) {
    uint32_t a;
    asm("{ .reg .u64 t; cvta.to.shared.u64 t, %1; cvt.u32.u64 %0, t; }" : "=r"(a) : "l"(p));
    return a;
}
static __device__ __forceinline__ uint32_t swz(uint32_t o) { return o ^ ((o >> 3) & 0x70); }

static __device__ __forceinline__ void cp16(uint32_t dst, const void* src) {
    asm volatile("cp.async.cg.shared.global [%0], [%1], 16;" :: "r"(dst), "l"(src) : "memory");
}
#define CP_COMMIT() asm volatile("cp.async.commit_group;" ::: "memory")
#define CP_WAIT0()  asm volatile("cp.async.wait_group 0;" ::: "memory")
#define CP_WAIT1()  asm volatile("cp.async.wait_group 1;" ::: "memory")

static __device__ __forceinline__ void ldsm_x4(uint32_t* r, uint32_t addr) {
    asm volatile("ldmatrix.sync.aligned.m8n8.x4.shared.b16 {%0,%1,%2,%3}, [%4];"
                 : "=r"(r[0]), "=r"(r[1]), "=r"(r[2]), "=r"(r[3]) : "r"(addr));
}
static __device__ __forceinline__ void hmma(float* c, const uint32_t* a, const uint32_t* b) {
    asm volatile(
        "mma.sync.aligned.m16n8k16.row.col.f32.f16.f16.f32 "
        "{%0,%1,%2,%3}, {%4,%5,%6,%7}, {%8,%9}, {%0,%1,%2,%3};"
        : "+f"(c[0]), "+f"(c[1]), "+f"(c[2]), "+f"(c[3])
        : "r"(a[0]), "r"(a[1]), "r"(a[2]), "r"(a[3]), "r"(b[0]), "r"(b[1]));
}

// ---------------------------------------------------------------------------
// Kernel 1: split 2*X and E into 2 fp16 terms each; compute ||e||^2
// ---------------------------------------------------------------------------
static __device__ __forceinline__ void split2(float v, __half& h0, __half& h1) {
    h0 = __float2half_rn(v);
    h1 = __float2half_rn(v - __half2float(h0));
}

__global__ void convert_kernel(const float* __restrict__ X, const float* __restrict__ E) {
    int row = blockIdx.x;
    int t = threadIdx.x;                     // 128
    size_t base = (size_t)row * DD + t * 4;
    {
        float4 v = *reinterpret_cast<const float4*>(X + base);
        float s[4] = {2.f * v.x, 2.f * v.y, 2.f * v.z, 2.f * v.w};
        __half h0[4], h1[4];
        #pragma unroll
        for (int i = 0; i < 4; i++) split2(s[i], h0[i], h1[i]);
        *reinterpret_cast<__half2*>(&g_X0[base])     = __half2{h0[0], h0[1]};
        *reinterpret_cast<__half2*>(&g_X0[base + 2]) = __half2{h0[2], h0[3]};
        *reinterpret_cast<__half2*>(&g_X1[base])     = __half2{h1[0], h1[1]};
        *reinterpret_cast<__half2*>(&g_X1[base + 2]) = __half2{h1[2], h1[3]};
    }
    {
        float4 v = *reinterpret_cast<const float4*>(E + base);
        float s[4] = {v.x, v.y, v.z, v.w};
        __half h0[4], h1[4];
        #pragma unroll
        for (int i = 0; i < 4; i++) split2(s[i], h0[i], h1[i]);
        *reinterpret_cast<__half2*>(&g_E0[base])     = __half2{h0[0], h0[1]};
        *reinterpret_cast<__half2*>(&g_E0[base + 2]) = __half2{h0[2], h0[3]};
        *reinterpret_cast<__half2*>(&g_E1[base])     = __half2{h1[0], h1[1]};
        *reinterpret_cast<__half2*>(&g_E1[base + 2]) = __half2{h1[2], h1[3]};

        float sq = v.x * v.x + v.y * v.y + v.z * v.z + v.w * v.w;
        #pragma unroll
        for (int o = 16; o; o >>= 1) sq += __shfl_down_sync(0xFFFFFFFFu, sq, o);
        __shared__ float ws[4];
        if ((t & 31) == 0) ws[t >> 5] = sq;
        __syncthreads();
        if (t == 0) g_esq[row] = ws[0] + ws[1] + ws[2] + ws[3];
    }
}

// ---------------------------------------------------------------------------
// Kernel 2: HMMA GEMM + per-row partial argmax.  grid (64, 32), 256 threads.
// ---------------------------------------------------------------------------
static __device__ __forceinline__ void load_stage(uint32_t sb, int s, int kc,
                                                  int m0, int cb0, int tid) {
    uint32_t stg = sb + OFF_STG + s * STG_BYTES;
    // A tiles: 128 rows x 64 cols per split
    #pragma unroll
    for (int tile = 0; tile < 2; tile++) {
        const __half* src_base = (tile == 0) ? g_X0 : g_X1;
        #pragma unroll
        for (int i = 0; i < 4; i++) {
            int cid = tid + i * 256;              // 0..1023
            int row = cid >> 3;
            int c16 = cid & 7;
            const __half* src = src_base + (size_t)(m0 + row) * DD + kc * BK + c16 * 8;
            uint32_t dst = stg + tile * 16384 + swz((uint32_t)(row * 128 + c16 * 16));
            cp16(dst, src);
        }
    }
    // B tiles: 256 rows x 64 cols per split
    #pragma unroll
    for (int tile = 0; tile < 2; tile++) {
        const __half* src_base = (tile == 0) ? g_E0 : g_E1;
        #pragma unroll
        for (int i = 0; i < 8; i++) {
            int cid = tid + i * 256;              // 0..2047
            int row = cid >> 3;
            int c16 = cid & 7;
            const __half* src = src_base + (size_t)(cb0 + row) * DD + kc * BK + c16 * 8;
            uint32_t dst = stg + 32768 + tile * 32768 + swz((uint32_t)(row * 128 + c16 * 16));
            cp16(dst, src);
        }
    }
    CP_COMMIT();
}

__global__ __launch_bounds__(256, 1)
void vq_mma_kernel() {
    extern __shared__ char smem[];
    const uint32_t sb = smem_u32(smem);
    const int tid = threadIdx.x;
    const int lane = tid & 31;
    const int wid = tid >> 5;
    const int warp_m = wid >> 2;         // 0..1  (64 rows each)
    const int warp_n = wid & 3;          // 0..3  (64 cols each)
    const int m0 = blockIdx.x * BMT;
    const int cb0 = blockIdx.y * BNT;

    float* es = reinterpret_cast<float*>(smem + OFF_ESQ);
    for (int i = tid; i < BNT; i += 256) es[i] = g_esq[cb0 + i];

    float acc[4][8][4];
    #pragma unroll
    for (int mf = 0; mf < 4; mf++)
        #pragma unroll
        for (int nf = 0; nf < 8; nf++)
            #pragma unroll
            for (int c = 0; c < 4; c++) acc[mf][nf][c] = 0.f;

    // precomputed smem addresses (lane-dependent parts)
    // A: row = warp_m*64 + mf*16 + (lane&15), kb = ks*32 + (lane>>4)*16
    // B: row = warp_n*64 + nfp*16 + ((lane>>4))*8 + (lane&7), kb = ks*32 + ((lane>>3)&1)*16
    const uint32_t a_row = (uint32_t)(warp_m * 64 + (lane & 15));
    const uint32_t a_kb  = (uint32_t)((lane >> 4) * 16);
    const uint32_t b_row = (uint32_t)(warp_n * 64 + (lane >> 4) * 8 + (lane & 7));
    const uint32_t b_kb  = (uint32_t)(((lane >> 3) & 1) * 16);

    load_stage(sb, 0, 0, m0, cb0, tid);

    for (int kc = 0; kc < NKC; kc++) {
        if (kc + 1 < NKC) { load_stage(sb, (kc + 1) & 1, kc + 1, m0, cb0, tid); CP_WAIT1(); }
        else CP_WAIT0();
        __syncthreads();

        uint32_t stg = sb + OFF_STG + (kc & 1) * STG_BYTES;
        uint32_t A0 = stg, A1 = stg + 16384, B0 = stg + 32768, B1 = stg + 65536;

        #pragma unroll
        for (int ks = 0; ks < 4; ks++) {
            const uint32_t kso = (uint32_t)(ks * 32);
            uint32_t a0[4][4], a1[4][4], b0[8][2], b1[8][2];
            // load A0 + B0 fragments
            #pragma unroll
            for (int mf = 0; mf < 4; mf++)
                ldsm_x4(a0[mf], A0 + swz((a_row + mf * 16) * 128 + kso + a_kb));
            #pragma unroll
            for (int nfp = 0; nfp < 4; nfp++)
                ldsm_x4(&b0[nfp * 2][0], B0 + swz((b_row + nfp * 16) * 128 + kso + b_kb));
            // product x0*e0
            #pragma unroll
            for (int mf = 0; mf < 4; mf++)
                #pragma unroll
                for (int nf = 0; nf < 8; nf++) hmma(acc[mf][nf], a0[mf], b0[nf]);
            // load B1, product x0*e1
            #pragma unroll
            for (int nfp = 0; nfp < 4; nfp++)
                ldsm_x4(&b1[nfp * 2][0], B1 + swz((b_row + nfp * 16) * 128 + kso + b_kb));
            #pragma unroll
            for (int mf = 0; mf < 4; mf++)
                #pragma unroll
                for (int nf = 0; nf < 8; nf++) hmma(acc[mf][nf], a0[mf], b1[nf]);
            // load A1, product x1*e0
            #pragma unroll
            for (int mf = 0; mf < 4; mf++)
                ldsm_x4(a1[mf], A1 + swz((a_row + mf * 16) * 128 + kso + a_kb));
            #pragma unroll
            for (int mf = 0; mf < 4; mf++)
                #pragma unroll
                for (int nf = 0; nf < 8; nf++) hmma(acc[mf][nf], a1[mf], b0[nf]);
        }
        __syncthreads();
    }

    // ---- epilogue: argmax over this CTA's 256 cols ----
    // slot = mf*2 + h ; row = warp_m*64 + mf*16 + (lane>>2) + h*8
    float best[8];
    int   bidx[8];
    #pragma unroll
    for (int i = 0; i < 8; i++) { best[i] = -3.4e38f; bidx[i] = 0; }

    #pragma unroll
    for (int mf = 0; mf < 4; mf++) {
        #pragma unroll
        for (int nf = 0; nf < 8; nf++) {
            int colb = warp_n * 64 + nf * 8 + (lane & 3) * 2;
            float s0 = acc[mf][nf][0] - es[colb];
            float s1 = acc[mf][nf][1] - es[colb + 1];
            float s2 = acc[mf][nf][2] - es[colb];
            float s3 = acc[mf][nf][3] - es[colb + 1];
            int sl0 = mf * 2, sl1 = mf * 2 + 1;
            if (s0 > best[sl0]) { best[sl0] = s0; bidx[sl0] = colb; }
            if (s1 > best[sl0]) { best[sl0] = s1; bidx[sl0] = colb + 1; }
            if (s2 > best[sl1]) { best[sl1] = s2; bidx[sl1] = colb; }
            if (s3 > best[sl1]) { best[sl1] = s3; bidx[sl1] = colb + 1; }
        }
    }
    // reduce across the 4 lanes holding the same rows (lane&3 varies)
    #pragma unroll
    for (int off = 1; off <= 2; off <<= 1) {
        #pragma unroll
        for (int i = 0; i < 8; i++) {
            float vv = __shfl_xor_sync(0xFFFFFFFFu, best[i], off);
            int   ii = __shfl_xor_sync(0xFFFFFFFFu, bidx[i], off);
            if (vv > best[i] || (vv == best[i] && ii < bidx[i])) {
                best[i] = vv; bidx[i] = ii;
            }
        }
    }
    float* rdv = reinterpret_cast<float*>(smem + OFF_RDV);
    int*   rdi = reinterpret_cast<int*>(smem + OFF_RDI);
    if ((lane & 3) == 0) {
        #pragma unroll
        for (int i = 0; i < 8; i++) {
            int row = warp_m * 64 + (i >> 1) * 16 + (lane >> 2) + (i & 1) * 8;
            rdv[row * 4 + warp_n] = best[i];
            rdi[row * 4 + warp_n] = bidx[i];
        }
    }
    __syncthreads();
    if (tid < BMT) {
        float bv = rdv[tid * 4];
        int   bi = rdi[tid * 4];
        #pragma unroll
        for (int w = 1; w < 4; w++) {
            float v  = rdv[tid * 4 + w];
            int   ii = rdi[tid * 4 + w];
            if (v > bv || (v == bv && ii < bi)) { bv = v; bi = ii; }
        }
        g_pval[blockIdx.y * NQ + m0 + tid] = bv;
        g_pidx[blockIdx.y * NQ + m0 + tid] = cb0 + bi;
    }
}

// ---------------------------------------------------------------------------
// Kernel 3: reduce 32 partials per row, gather codebook row, write index
// ---------------------------------------------------------------------------
__global__ void finalize_kernel(const float* __restrict__ E,
                                float* __restrict__ out, int write_idx) {
    int row = blockIdx.x;
    __shared__ float sv[NSPLITC];
    __shared__ int   si[NSPLITC];
    __shared__ int   s_idx;
    int t = threadIdx.x;
    if (t < NSPLITC) {
        sv[t] = g_pval[t * NQ + row];
        si[t] = g_pidx[t * NQ + row];
    }
    __syncthreads();
    if (t == 0) {
        float bv = sv[0]; int bi = si[0];
        #pragma unroll
        for (int s = 1; s < NSPLITC; s++) {
            float v = sv[s]; int ii = si[s];
            if (v > bv || (v == bv && ii < bi)) { bv = v; bi = ii; }
        }
        s_idx = bi;
        if (write_idx) out[(size_t)NQ * DD + row] = (float)bi;
    }
    __syncthreads();
    int idx = s_idx;
    float4 v = *reinterpret_cast<const float4*>(E + (size_t)idx * DD + t * 4);
    *reinterpret_cast<float4*>(out + (size_t)row * DD + t * 4) = v;
}

// ---------------------------------------------------------------------------
extern "C" void kernel_launch(void* const* d_in, const int* in_sizes, int n_in,
                              void* d_out, int out_size) {
    const float* X = (const float*)d_in[0];
    const float* E = (const float*)d_in[1];
    float* out = (float*)d_out;

    static int attr_done = 0;
    if (!attr_done) {
        cudaFuncSetAttribute(vq_mma_kernel,
                             cudaFuncAttributeMaxDynamicSharedMemorySize, SMEM_TOTAL);
        attr_done = 1;
    }

    convert_kernel<<<NQ, 128>>>(X, E);
    vq_mma_kernel<<<dim3(NQ / BMT, NC / BNT), 256, SMEM_TOTAL>>>();
    int write_idx = (out_size >= NQ * DD + NQ) ? 1 : 0;
    finalize_kernel<<<NQ, 128>>>(E, out, write_idx);
}

// round 5
// speedup vs baseline: 4.8369x; 1.1498x over previous
#include <cuda_runtime.h>
#include <cuda_fp16.h>
#include <cstdint>

// SimpleCodebook VQ, R5: 1-product fp16 HMMA approximate pass + exact fp64
// rescore of the (rare) ambiguous rows.
//   approx[n,k] = fp16(2x_n).fp16(e_k) - ||e_k||^2   (fp32 accumulate)
//   |approx - true| <= ~0.1 (30-sigma bound 0.5 used as margin DELTA).
//   Pass1 keeps top-2 per (row, 256-col chunk); finalize filters by
//   M - DELTA and fp64-rescores if more than one candidate survives.

#define NQ 8192
#define NC 8192
#define DD 512
#define BMT 128             // CTA tile M
#define BNT 256             // CTA tile N
#define BK  64              // K chunk (fp16) -> 128B rows
#define NKC (DD / BK)       // 8
#define NCHUNK (NC / BNT)   // 32
#define DELTA 0.5f

#define NSTG 4
#define STG_BYTES 49152     // A0(16K) + B0(32K)
#define OFF_ESQ 0           // 256 floats = 1KB
#define OFF_RED 1024        // 4 arrays x 128x4 x 4B = 8KB
#define OFF_STG 9216
#define SMEM_TOTAL (OFF_STG + NSTG * STG_BYTES)   // 205824

// ---- device global scratch ----
__device__ __half g_X0[NQ * DD];
__device__ __half g_E0[NC * DD];
__device__ float  g_esq[NC];
__device__ float4 g_cand[NCHUNK * NQ];   // (v1, idx1_bits, v2, idx2_bits)

static __device__ __forceinline__ uint32_t smem_u32(const void* p) {
    uint32_t a;
    asm("{ .reg .u64 t; cvta.to.shared.u64 t, %1; cvt.u32.u64 %0, t; }" : "=r"(a) : "l"(p));
    return a;
}
static __device__ __forceinline__ uint32_t swz(uint32_t o) { return o ^ ((o >> 3) & 0x70); }

static __device__ __forceinline__ void cp16(uint32_t dst, const void* src) {
    asm volatile("cp.async.cg.shared.global [%0], [%1], 16;" :: "r"(dst), "l"(src) : "memory");
}
#define CP_COMMIT() asm volatile("cp.async.commit_group;" ::: "memory")
#define CP_WAIT0()  asm volatile("cp.async.wait_group 0;" ::: "memory")
#define CP_WAIT1()  asm volatile("cp.async.wait_group 1;" ::: "memory")
#define CP_WAIT2()  asm volatile("cp.async.wait_group 2;" ::: "memory")

static __device__ __forceinline__ void ldsm_x4(uint32_t* r, uint32_t addr) {
    asm volatile("ldmatrix.sync.aligned.m8n8.x4.shared.b16 {%0,%1,%2,%3}, [%4];"
                 : "=r"(r[0]), "=r"(r[1]), "=r"(r[2]), "=r"(r[3]) : "r"(addr));
}
static __device__ __forceinline__ void hmma(float* c, const uint32_t* a, const uint32_t* b) {
    asm volatile(
        "mma.sync.aligned.m16n8k16.row.col.f32.f16.f16.f32 "
        "{%0,%1,%2,%3}, {%4,%5,%6,%7}, {%8,%9}, {%0,%1,%2,%3};"
        : "+f"(c[0]), "+f"(c[1]), "+f"(c[2]), "+f"(c[3])
        : "r"(a[0]), "r"(a[1]), "r"(a[2]), "r"(a[3]), "r"(b[0]), "r"(b[1]));
}

// ---------------------------------------------------------------------------
// Kernel 1: X0 = fp16(2x), E0 = fp16(e), esq = ||e||^2 (fp32)
// ---------------------------------------------------------------------------
__global__ void convert_kernel(const float* __restrict__ X, const float* __restrict__ E) {
    int row = blockIdx.x;
    int t = threadIdx.x;                     // 128
    size_t base = (size_t)row * DD + t * 4;
    {
        float4 v = *reinterpret_cast<const float4*>(X + base);
        __half2 h01 = __floats2half2_rn(2.f * v.x, 2.f * v.y);
        __half2 h23 = __floats2half2_rn(2.f * v.z, 2.f * v.w);
        *reinterpret_cast<__half2*>(&g_X0[base])     = h01;
        *reinterpret_cast<__half2*>(&g_X0[base + 2]) = h23;
    }
    {
        float4 v = *reinterpret_cast<const float4*>(E + base);
        __half2 h01 = __floats2half2_rn(v.x, v.y);
        __half2 h23 = __floats2half2_rn(v.z, v.w);
        *reinterpret_cast<__half2*>(&g_E0[base])     = h01;
        *reinterpret_cast<__half2*>(&g_E0[base + 2]) = h23;

        float sq = v.x * v.x + v.y * v.y + v.z * v.z + v.w * v.w;
        #pragma unroll
        for (int o = 16; o; o >>= 1) sq += __shfl_down_sync(0xFFFFFFFFu, sq, o);
        __shared__ float ws[4];
        if ((t & 31) == 0) ws[t >> 5] = sq;
        __syncthreads();
        if (t == 0) g_esq[row] = ws[0] + ws[1] + ws[2] + ws[3];
    }
}

// ---------------------------------------------------------------------------
// Kernel 2: approx HMMA GEMM + top-2 per (row, chunk). grid (64,32), 256 thr.
// ---------------------------------------------------------------------------
static __device__ __forceinline__ void load_stage(uint32_t sb, int s, int kc,
                                                  int m0, int cb0, int tid) {
    uint32_t stg = sb + OFF_STG + s * STG_BYTES;
    // A0: 128 rows x 64 cols
    #pragma unroll
    for (int i = 0; i < 4; i++) {
        int cid = tid + i * 256;              // 0..1023
        int row = cid >> 3;
        int c16 = cid & 7;
        const __half* src = g_X0 + (size_t)(m0 + row) * DD + kc * BK + c16 * 8;
        cp16(stg + swz((uint32_t)(row * 128 + c16 * 16)), src);
    }
    // B0: 256 rows x 64 cols
    #pragma unroll
    for (int i = 0; i < 8; i++) {
        int cid = tid + i * 256;              // 0..2047
        int row = cid >> 3;
        int c16 = cid & 7;
        const __half* src = g_E0 + (size_t)(cb0 + row) * DD + kc * BK + c16 * 8;
        cp16(stg + 16384 + swz((uint32_t)(row * 128 + c16 * 16)), src);
    }
    CP_COMMIT();
}

static __device__ __forceinline__ void upd2(float v, int i, float& v1, int& i1,
                                            float& v2, int& i2) {
    if (v > v1 || (v == v1 && i < i1)) {
        v2 = v1; i2 = i1; v1 = v; i1 = i;
    } else if (v > v2 || (v == v2 && i < i2)) {
        v2 = v; i2 = i;
    }
}

__global__ __launch_bounds__(256, 1)
void vq_mma_kernel() {
    extern __shared__ char smem[];
    const uint32_t sb = smem_u32(smem);
    const int tid = threadIdx.x;
    const int lane = tid & 31;
    const int wid = tid >> 5;
    const int warp_m = wid >> 2;         // 0..1  (64 rows each)
    const int warp_n = wid & 3;          // 0..3  (64 cols each)
    const int m0 = blockIdx.x * BMT;
    const int cb0 = blockIdx.y * BNT;

    float* es = reinterpret_cast<float*>(smem + OFF_ESQ);
    for (int i = tid; i < BNT; i += 256) es[i] = g_esq[cb0 + i];

    float acc[4][8][4];
    #pragma unroll
    for (int mf = 0; mf < 4; mf++)
        #pragma unroll
        for (int nf = 0; nf < 8; nf++)
            #pragma unroll
            for (int c = 0; c < 4; c++) acc[mf][nf][c] = 0.f;

    const uint32_t a_row = (uint32_t)(warp_m * 64 + (lane & 15));
    const uint32_t a_kb  = (uint32_t)((lane >> 4) * 16);
    const uint32_t b_row = (uint32_t)(warp_n * 64 + (lane >> 4) * 8 + (lane & 7));
    const uint32_t b_kb  = (uint32_t)(((lane >> 3) & 1) * 16);

    load_stage(sb, 0, 0, m0, cb0, tid);
    load_stage(sb, 1, 1, m0, cb0, tid);
    load_stage(sb, 2, 2, m0, cb0, tid);

    for (int kc = 0; kc < NKC; kc++) {
        if (kc < 6) CP_WAIT2(); else if (kc == 6) CP_WAIT1(); else CP_WAIT0();
        __syncthreads();
        if (kc + 3 < NKC) load_stage(sb, (kc + 3) & 3, kc + 3, m0, cb0, tid);

        uint32_t stg = sb + OFF_STG + (kc & 3) * STG_BYTES;
        uint32_t A0 = stg, B0 = stg + 16384;

        #pragma unroll
        for (int ks = 0; ks < 4; ks++) {
            const uint32_t kso = (uint32_t)(ks * 32);
            uint32_t a0[4][4], b0[8][2];
            #pragma unroll
            for (int mf = 0; mf < 4; mf++)
                ldsm_x4(a0[mf], A0 + swz((a_row + mf * 16) * 128 + kso + a_kb));
            #pragma unroll
            for (int nfp = 0; nfp < 4; nfp++)
                ldsm_x4(&b0[nfp * 2][0], B0 + swz((b_row + nfp * 16) * 128 + kso + b_kb));
            #pragma unroll
            for (int mf = 0; mf < 4; mf++)
                #pragma unroll
                for (int nf = 0; nf < 8; nf++) hmma(acc[mf][nf], a0[mf], b0[nf]);
        }
    }
    __syncthreads();   // done with stage buffers before smem reuse below

    // ---- epilogue: top-2 over this CTA's 256 cols per row ----
    float v1[8], v2[8];
    int   i1[8], i2[8];
    #pragma unroll
    for (int i = 0; i < 8; i++) {
        v1[i] = -3.4e38f; v2[i] = -3.4e38f; i1[i] = 0x7FFFFFF; i2[i] = 0x7FFFFFF;
    }

    #pragma unroll
    for (int mf = 0; mf < 4; mf++) {
        #pragma unroll
        for (int nf = 0; nf < 8; nf++) {
            int colb = warp_n * 64 + nf * 8 + (lane & 3) * 2;
            float s0 = acc[mf][nf][0] - es[colb];
            float s1 = acc[mf][nf][1] - es[colb + 1];
            float s2 = acc[mf][nf][2] - es[colb];
            float s3 = acc[mf][nf][3] - es[colb + 1];
            int sl0 = mf * 2, sl1 = mf * 2 + 1;
            upd2(s0, colb,     v1[sl0], i1[sl0], v2[sl0], i2[sl0]);
            upd2(s1, colb + 1, v1[sl0], i1[sl0], v2[sl0], i2[sl0]);
            upd2(s2, colb,     v1[sl1], i1[sl1], v2[sl1], i2[sl1]);
            upd2(s3, colb + 1, v1[sl1], i1[sl1], v2[sl1], i2[sl1]);
        }
    }
    // merge across the 4 lanes holding the same rows
    #pragma unroll
    for (int off = 1; off <= 2; off <<= 1) {
        #pragma unroll
        for (int i = 0; i < 8; i++) {
            float ov1 = __shfl_xor_sync(0xFFFFFFFFu, v1[i], off);
            int   oi1 = __shfl_xor_sync(0xFFFFFFFFu, i1[i], off);
            float ov2 = __shfl_xor_sync(0xFFFFFFFFu, v2[i], off);
            int   oi2 = __shfl_xor_sync(0xFFFFFFFFu, i2[i], off);
            upd2(ov1, oi1, v1[i], i1[i], v2[i], i2[i]);
            upd2(ov2, oi2, v1[i], i1[i], v2[i], i2[i]);
        }
    }
    float* rv1 = reinterpret_cast<float*>(smem + OFF_RED);
    int*   ri1 = reinterpret_cast<int*>(smem + OFF_RED + 2048);
    float* rv2 = reinterpret_cast<float*>(smem + OFF_RED + 4096);
    int*   ri2 = reinterpret_cast<int*>(smem + OFF_RED + 6144);
    if ((lane & 3) == 0) {
        #pragma unroll
        for (int i = 0; i < 8; i++) {
            int row = warp_m * 64 + (i >> 1) * 16 + (lane >> 2) + (i & 1) * 8;
            rv1[row * 4 + warp_n] = v1[i];
            ri1[row * 4 + warp_n] = i1[i];
            rv2[row * 4 + warp_n] = v2[i];
            ri2[row * 4 + warp_n] = i2[i];
        }
    }
    __syncthreads();
    if (tid < BMT) {
        float bv1 = -3.4e38f, bv2 = -3.4e38f;
        int   bi1 = 0x7FFFFFF, bi2 = 0x7FFFFFF;
        #pragma unroll
        for (int w = 0; w < 4; w++) {
            upd2(rv1[tid * 4 + w], ri1[tid * 4 + w], bv1, bi1, bv2, bi2);
            upd2(rv2[tid * 4 + w], ri2[tid * 4 + w], bv1, bi1, bv2, bi2);
        }
        g_cand[blockIdx.y * NQ + m0 + tid] =
            make_float4(bv1, __int_as_float(cb0 + bi1), bv2, __int_as_float(cb0 + bi2));
    }
}

// ---------------------------------------------------------------------------
// Kernel 3: filter candidates, fp64-rescore ambiguous rows, gather output.
//   one block (256 thr) per row
// ---------------------------------------------------------------------------
__global__ __launch_bounds__(256)
void finalize_kernel(const float* __restrict__ X, const float* __restrict__ E,
                     float* __restrict__ out, int write_idx) {
    int row = blockIdx.x;
    int t = threadIdx.x;
    __shared__ float4 ent[NCHUNK];
    __shared__ int    cidx[64];
    __shared__ double csc[64];
    __shared__ int    s_cnt, s_win;

    if (t < NCHUNK) ent[t] = g_cand[t * NQ + row];
    __syncthreads();

    if (t == 0) {
        float M = -3.4e38f;
        #pragma unroll
        for (int c = 0; c < NCHUNK; c++) M = fmaxf(M, ent[c].x);
        float thr = M - DELTA;
        int cnt = 0;
        for (int c = 0; c < NCHUNK; c++) {
            if (ent[c].x >= thr) cidx[cnt++] = __float_as_int(ent[c].y);
            if (ent[c].z >= thr) cidx[cnt++] = __float_as_int(ent[c].w);
        }
        s_cnt = cnt;
        if (cnt == 1) s_win = cidx[0];
    }
    __syncthreads();

    int cnt = s_cnt;
    if (cnt > 1) {
        // exact fp64 rescore of each candidate: 2*x.e - ||e||^2
        int wid = t >> 5, lane = t & 31;
        for (int c = wid; c < cnt; c += 8) {
            const float* xr = X + (size_t)row * DD;
            const float* er = E + (size_t)cidx[c] * DD;
            double xe = 0.0, ee = 0.0;
            #pragma unroll
            for (int q = 0; q < DD / 32; q++) {
                double xv = (double)xr[q * 32 + lane];
                double ev = (double)er[q * 32 + lane];
                xe += xv * ev;
                ee += ev * ev;
            }
            double sc = 2.0 * xe - ee;
            #pragma unroll
            for (int o = 16; o; o >>= 1) sc += __shfl_down_sync(0xFFFFFFFFu, sc, o);
            if (lane == 0) csc[c] = sc;
        }
        __syncthreads();
        if (t == 0) {
            double bv = csc[0];
            int bi = cidx[0];
            for (int c = 1; c < cnt; c++) {
                if (csc[c] > bv || (csc[c] == bv && cidx[c] < bi)) {
                    bv = csc[c]; bi = cidx[c];
                }
            }
            s_win = bi;
        }
        __syncthreads();
    }

    int idx = s_win;
    if (t == 0 && write_idx) out[(size_t)NQ * DD + row] = (float)idx;
    if (t < 128) {
        float4 v = *reinterpret_cast<const float4*>(E + (size_t)idx * DD + t * 4);
        *reinterpret_cast<float4*>(out + (size_t)row * DD + t * 4) = v;
    }
}

// ---------------------------------------------------------------------------
extern "C" void kernel_launch(void* const* d_in, const int* in_sizes, int n_in,
                              void* d_out, int out_size) {
    const float* X = (const float*)d_in[0];
    const float* E = (const float*)d_in[1];
    float* out = (float*)d_out;

    static int attr_done = 0;
    if (!attr_done) {
        cudaFuncSetAttribute(vq_mma_kernel,
                             cudaFuncAttributeMaxDynamicSharedMemorySize, SMEM_TOTAL);
        attr_done = 1;
    }

    convert_kernel<<<NQ, 128>>>(X, E);
    vq_mma_kernel<<<dim3(NQ / BMT, NC / BNT), 256, SMEM_TOTAL>>>();
    int write_idx = (out_size >= NQ * DD + NQ) ? 1 : 0;
    finalize_kernel<<<NQ, 256>>>(X, E, out, write_idx);
}

// round 7
// speedup vs baseline: 6.0978x; 1.2607x over previous
#include <cuda_runtime.h>
#include <cuda_fp16.h>
#include <cstdint>

// SimpleCodebook VQ, R7: 1-product fp16 HMMA approximate pass (2 CTAs/SM)
// + exact fp64 rescore of rare ambiguous rows.  Fixes R6's broken swizzle
// hoist: swz(base+k) = base + (k ^ m(row)) with m = ((row*128)>>3)&0x70.

#define NQ 8192
#define NC 8192
#define DD 512
#define BMT 128             // CTA tile M
#define BNT 128             // CTA tile N
#define BK  64              // K chunk (fp16) -> 128B rows
#define NKC (DD / BK)       // 8
#define NCHUNK (NC / BNT)   // 64
#define DELTA 0.5f

#define NSTG 3
#define STG_BYTES 32768     // A(16K) + B(16K)
#define OFF_ESQ 0           // 128 floats = 512B
#define OFF_RED 512         // 4 arrays x 128x4 x 4B = 8KB
#define OFF_STG 8704
#define SMEM_TOTAL (OFF_STG + NSTG * STG_BYTES)   // 107008 (~105KB) -> 2 CTAs/SM

// ---- device global scratch ----
__device__ __half g_X0[NQ * DD];
__device__ __half g_E0[NC * DD];
__device__ float  g_esq[NC];
__device__ float4 g_cand[NCHUNK * NQ];   // (v1, idx1_bits, v2, idx2_bits)

static __device__ __forceinline__ uint32_t smem_u32(const void* p) {
    uint32_t a;
    asm("{ .reg .u64 t; cvta.to.shared.u64 t, %1; cvt.u32.u64 %0, t; }" : "=r"(a) : "l"(p));
    return a;
}
static __device__ __forceinline__ uint32_t swz(uint32_t o) { return o ^ ((o >> 3) & 0x70); }

static __device__ __forceinline__ void cp16(uint32_t dst, const void* src) {
    asm volatile("cp.async.cg.shared.global [%0], [%1], 16;" :: "r"(dst), "l"(src) : "memory");
}
#define CP_COMMIT() asm volatile("cp.async.commit_group;" ::: "memory")
#define CP_WAIT0()  asm volatile("cp.async.wait_group 0;" ::: "memory")
#define CP_WAIT1()  asm volatile("cp.async.wait_group 1;" ::: "memory")

static __device__ __forceinline__ void ldsm_x4(uint32_t* r, uint32_t addr) {
    asm volatile("ldmatrix.sync.aligned.m8n8.x4.shared.b16 {%0,%1,%2,%3}, [%4];"
                 : "=r"(r[0]), "=r"(r[1]), "=r"(r[2]), "=r"(r[3]) : "r"(addr));
}
static __device__ __forceinline__ void hmma(float* c, const uint32_t* a, const uint32_t* b) {
    asm volatile(
        "mma.sync.aligned.m16n8k16.row.col.f32.f16.f16.f32 "
        "{%0,%1,%2,%3}, {%4,%5,%6,%7}, {%8,%9}, {%0,%1,%2,%3};"
        : "+f"(c[0]), "+f"(c[1]), "+f"(c[2]), "+f"(c[3])
        : "r"(a[0]), "r"(a[1]), "r"(a[2]), "r"(a[3]), "r"(b[0]), "r"(b[1]));
}

// ---------------------------------------------------------------------------
// Kernel 1: X0 = fp16(2x), E0 = fp16(e), esq = ||e||^2 (fp32)
// ---------------------------------------------------------------------------
__global__ void convert_kernel(const float* __restrict__ X, const float* __restrict__ E) {
    int row = blockIdx.x;
    int t = threadIdx.x;                     // 128
    size_t base = (size_t)row * DD + t * 4;
    {
        float4 v = *reinterpret_cast<const float4*>(X + base);
        __half2 h01 = __floats2half2_rn(2.f * v.x, 2.f * v.y);
        __half2 h23 = __floats2half2_rn(2.f * v.z, 2.f * v.w);
        *reinterpret_cast<__half2*>(&g_X0[base])     = h01;
        *reinterpret_cast<__half2*>(&g_X0[base + 2]) = h23;
    }
    {
        float4 v = *reinterpret_cast<const float4*>(E + base);
        __half2 h01 = __floats2half2_rn(v.x, v.y);
        __half2 h23 = __floats2half2_rn(v.z, v.w);
        *reinterpret_cast<__half2*>(&g_E0[base])     = h01;
        *reinterpret_cast<__half2*>(&g_E0[base + 2]) = h23;

        float sq = v.x * v.x + v.y * v.y + v.z * v.z + v.w * v.w;
        #pragma unroll
        for (int o = 16; o; o >>= 1) sq += __shfl_down_sync(0xFFFFFFFFu, sq, o);
        __shared__ float ws[4];
        if ((t & 31) == 0) ws[t >> 5] = sq;
        __syncthreads();
        if (t == 0) g_esq[row] = ws[0] + ws[1] + ws[2] + ws[3];
    }
}

// ---------------------------------------------------------------------------
// Kernel 2: approx HMMA GEMM + top-2 per (row, chunk). grid (64,64), 256 thr,
//           2 CTAs/SM (4 warps per SMSP) for latency hiding.
// ---------------------------------------------------------------------------
static __device__ __forceinline__ void load_stage(uint32_t sb, int s, int kc,
                                                  int m0, int cb0, int tid) {
    uint32_t stg = sb + OFF_STG + s * STG_BYTES;
    #pragma unroll
    for (int i = 0; i < 4; i++) {
        int cid = tid + i * 256;              // 0..1023
        int row = cid >> 3;
        int c16 = cid & 7;
        const __half* src = g_X0 + (size_t)(m0 + row) * DD + kc * BK + c16 * 8;
        cp16(stg + swz((uint32_t)(row * 128 + c16 * 16)), src);
    }
    #pragma unroll
    for (int i = 0; i < 4; i++) {
        int cid = tid + i * 256;
        int row = cid >> 3;
        int c16 = cid & 7;
        const __half* src = g_E0 + (size_t)(cb0 + row) * DD + kc * BK + c16 * 8;
        cp16(stg + 16384 + swz((uint32_t)(row * 128 + c16 * 16)), src);
    }
    CP_COMMIT();
}

static __device__ __forceinline__ void upd2(float v, int i, float& v1, int& i1,
                                            float& v2, int& i2) {
    if (v > v1 || (v == v1 && i < i1)) {
        v2 = v1; i2 = i1; v1 = v; i1 = i;
    } else if (v > v2 || (v == v2 && i < i2)) {
        v2 = v; i2 = i;
    }
}

__global__ __launch_bounds__(256, 2)
void vq_mma_kernel() {
    extern __shared__ char smem[];
    const uint32_t sb = smem_u32(smem);
    const int tid = threadIdx.x;
    const int lane = tid & 31;
    const int wid = tid >> 5;
    const int warp_m = wid >> 2;         // 0..1  (64 rows each)
    const int warp_n = wid & 3;          // 0..3  (32 cols each)
    const int m0 = blockIdx.x * BMT;
    const int cb0 = blockIdx.y * BNT;

    float* es = reinterpret_cast<float*>(smem + OFF_ESQ);
    for (int i = tid; i < BNT; i += 256) es[i] = g_esq[cb0 + i];

    float acc[4][4][4];
    #pragma unroll
    for (int mf = 0; mf < 4; mf++)
        #pragma unroll
        for (int nf = 0; nf < 4; nf++)
            #pragma unroll
            for (int c = 0; c < 4; c++) acc[mf][nf][c] = 0.f;

    // correct swizzle hoist: addr = stg + base + ((kso + kb) ^ m(row)),
    // base = row*128 (low 7 bits zero), m = ((row*128)>>3) & 0x70
    const uint32_t a_row = (uint32_t)(warp_m * 64 + (lane & 15));
    const uint32_t a_kb  = (uint32_t)((lane >> 4) * 16);
    const uint32_t b_row = (uint32_t)(warp_n * 32 + (lane >> 4) * 8 + (lane & 7));
    const uint32_t b_kb  = (uint32_t)(((lane >> 3) & 1) * 16);
    uint32_t abase[4], am[4], bbase[2], bm[2];
    #pragma unroll
    for (int mf = 0; mf < 4; mf++) {
        uint32_t b = (a_row + mf * 16) * 128;
        abase[mf] = b;
        am[mf] = (b >> 3) & 0x70;
    }
    #pragma unroll
    for (int nfp = 0; nfp < 2; nfp++) {
        uint32_t b = (b_row + nfp * 16) * 128;
        bbase[nfp] = 16384 + b;
        bm[nfp] = (b >> 3) & 0x70;
    }

    load_stage(sb, 0, 0, m0, cb0, tid);
    load_stage(sb, 1, 1, m0, cb0, tid);

    for (int kc = 0; kc < NKC; kc++) {
        if (kc == NKC - 1) CP_WAIT0(); else CP_WAIT1();
        __syncthreads();
        if (kc + 2 < NKC) load_stage(sb, (kc + 2) % NSTG, kc + 2, m0, cb0, tid);

        uint32_t stg = sb + OFF_STG + (kc % NSTG) * STG_BYTES;

        #pragma unroll
        for (int ks = 0; ks < 4; ks++) {
            const uint32_t ka = (uint32_t)(ks * 32) + a_kb;
            const uint32_t kb = (uint32_t)(ks * 32) + b_kb;
            uint32_t a0[4][4], b0[4][2];
            #pragma unroll
            for (int mf = 0; mf < 4; mf++)
                ldsm_x4(a0[mf], stg + abase[mf] + (ka ^ am[mf]));
            #pragma unroll
            for (int nfp = 0; nfp < 2; nfp++)
                ldsm_x4(&b0[nfp * 2][0], stg + bbase[nfp] + (kb ^ bm[nfp]));
            #pragma unroll
            for (int mf = 0; mf < 4; mf++)
                #pragma unroll
                for (int nf = 0; nf < 4; nf++) hmma(acc[mf][nf], a0[mf], b0[nf]);
        }
    }
    __syncthreads();   // done with stage buffers before smem reuse below

    // ---- epilogue: top-2 over this CTA's 128 cols per row ----
    float v1[8], v2[8];
    int   i1[8], i2[8];
    #pragma unroll
    for (int i = 0; i < 8; i++) {
        v1[i] = -3.4e38f; v2[i] = -3.4e38f; i1[i] = 0x7FFFFFF; i2[i] = 0x7FFFFFF;
    }

    #pragma unroll
    for (int mf = 0; mf < 4; mf++) {
        #pragma unroll
        for (int nf = 0; nf < 4; nf++) {
            int colb = warp_n * 32 + nf * 8 + (lane & 3) * 2;
            float s0 = acc[mf][nf][0] - es[colb];
            float s1 = acc[mf][nf][1] - es[colb + 1];
            float s2 = acc[mf][nf][2] - es[colb];
            float s3 = acc[mf][nf][3] - es[colb + 1];
            int sl0 = mf * 2, sl1 = mf * 2 + 1;
            upd2(s0, colb,     v1[sl0], i1[sl0], v2[sl0], i2[sl0]);
            upd2(s1, colb + 1, v1[sl0], i1[sl0], v2[sl0], i2[sl0]);
            upd2(s2, colb,     v1[sl1], i1[sl1], v2[sl1], i2[sl1]);
            upd2(s3, colb + 1, v1[sl1], i1[sl1], v2[sl1], i2[sl1]);
        }
    }
    // merge across the 4 lanes holding the same rows
    #pragma unroll
    for (int off = 1; off <= 2; off <<= 1) {
        #pragma unroll
        for (int i = 0; i < 8; i++) {
            float ov1 = __shfl_xor_sync(0xFFFFFFFFu, v1[i], off);
            int   oi1 = __shfl_xor_sync(0xFFFFFFFFu, i1[i], off);
            float ov2 = __shfl_xor_sync(0xFFFFFFFFu, v2[i], off);
            int   oi2 = __shfl_xor_sync(0xFFFFFFFFu, i2[i], off);
            upd2(ov1, oi1, v1[i], i1[i], v2[i], i2[i]);
            upd2(ov2, oi2, v1[i], i1[i], v2[i], i2[i]);
        }
    }
    float* rv1 = reinterpret_cast<float*>(smem + OFF_RED);
    int*   ri1 = reinterpret_cast<int*>(smem + OFF_RED + 2048);
    float* rv2 = reinterpret_cast<float*>(smem + OFF_RED + 4096);
    int*   ri2 = reinterpret_cast<int*>(smem + OFF_RED + 6144);
    if ((lane & 3) == 0) {
        #pragma unroll
        for (int i = 0; i < 8; i++) {
            int row = warp_m * 64 + (i >> 1) * 16 + (lane >> 2) + (i & 1) * 8;
            rv1[row * 4 + warp_n] = v1[i];
            ri1[row * 4 + warp_n] = i1[i];
            rv2[row * 4 + warp_n] = v2[i];
            ri2[row * 4 + warp_n] = i2[i];
        }
    }
    __syncthreads();
    if (tid < BMT) {
        float bv1 = -3.4e38f, bv2 = -3.4e38f;
        int   bi1 = 0x7FFFFFF, bi2 = 0x7FFFFFF;
        #pragma unroll
        for (int w = 0; w < 4; w++) {
            upd2(rv1[tid * 4 + w], ri1[tid * 4 + w], bv1, bi1, bv2, bi2);
            upd2(rv2[tid * 4 + w], ri2[tid * 4 + w], bv1, bi1, bv2, bi2);
        }
        g_cand[blockIdx.y * NQ + m0 + tid] =
            make_float4(bv1, __int_as_float(cb0 + bi1), bv2, __int_as_float(cb0 + bi2));
    }
}

// ---------------------------------------------------------------------------
// Kernel 3: filter candidates, fp64-rescore ambiguous rows, gather output.
// ---------------------------------------------------------------------------
__global__ __launch_bounds__(256)
void finalize_kernel(const float* __restrict__ X, const float* __restrict__ E,
                     float* __restrict__ out, int write_idx) {
    int row = blockIdx.x;
    int t = threadIdx.x;
    __shared__ float4 ent[NCHUNK];
    __shared__ int    cidx[2 * NCHUNK];
    __shared__ double csc[2 * NCHUNK];
    __shared__ int    s_cnt, s_win;

    if (t < NCHUNK) ent[t] = g_cand[t * NQ + row];
    __syncthreads();

    if (t == 0) {
        float M = -3.4e38f;
        #pragma unroll
        for (int c = 0; c < NCHUNK; c++) M = fmaxf(M, ent[c].x);
        float thr = M - DELTA;
        int cnt = 0;
        for (int c = 0; c < NCHUNK; c++) {
            if (ent[c].x >= thr) cidx[cnt++] = __float_as_int(ent[c].y);
            if (ent[c].z >= thr) cidx[cnt++] = __float_as_int(ent[c].w);
        }
        s_cnt = cnt;
        if (cnt == 1) s_win = cidx[0];
    }
    __syncthreads();

    int cnt = s_cnt;
    if (cnt > 1) {
        int wid = t >> 5, lane = t & 31;
        for (int c = wid; c < cnt; c += 8) {
            const float* xr = X + (size_t)row * DD;
            const float* er = E + (size_t)cidx[c] * DD;
            double xe = 0.0, ee = 0.0;
            #pragma unroll
            for (int q = 0; q < DD / 32; q++) {
                double xv = (double)xr[q * 32 + lane];
                double ev = (double)er[q * 32 + lane];
                xe += xv * ev;
                ee += ev * ev;
            }
            double sc = 2.0 * xe - ee;
            #pragma unroll
            for (int o = 16; o; o >>= 1) sc += __shfl_down_sync(0xFFFFFFFFu, sc, o);
            if (lane == 0) csc[c] = sc;
        }
        __syncthreads();
        if (t == 0) {
            double bv = csc[0];
            int bi = cidx[0];
            for (int c = 1; c < cnt; c++) {
                if (csc[c] > bv || (csc[c] == bv && cidx[c] < bi)) {
                    bv = csc[c]; bi = cidx[c];
                }
            }
            s_win = bi;
        }
        __syncthreads();
    }

    int idx = s_win;
    if (t == 0 && write_idx) out[(size_t)NQ * DD + row] = (float)idx;
    if (t < 128) {
        float4 v = *reinterpret_cast<const float4*>(E + (size_t)idx * DD + t * 4);
        *reinterpret_cast<float4*>(out + (size_t)row * DD + t * 4) = v;
    }
}

// ---------------------------------------------------------------------------
extern "C" void kernel_launch(void* const* d_in, const int* in_sizes, int n_in,
                              void* d_out, int out_size) {
    const float* X = (const float*)d_in[0];
    const float* E = (const float*)d_in[1];
    float* out = (float*)d_out;

    static int attr_done = 0;
    if (!attr_done) {
        cudaFuncSetAttribute(vq_mma_kernel,
                             cudaFuncAttributeMaxDynamicSharedMemorySize, SMEM_TOTAL);
        attr_done = 1;
    }

    convert_kernel<<<NQ, 128>>>(X, E);
    vq_mma_kernel<<<dim3(NQ / BMT, NC / BNT), 256, SMEM_TOTAL>>>();
    int write_idx = (out_size >= NQ * DD + NQ) ? 1 : 0;
    finalize_kernel<<<NQ, 256>>>(X, E, out, write_idx);
}